// round 8
// baseline (speedup 1.0000x reference)
#include <cuda_runtime.h>
#include <cuda_bf16.h>
#include <cuda_fp16.h>
#include <math.h>
#include <stdint.h>

#define NN 50000
#define EE 1600000
#define FF 256
#define KHOP 3
#define GN 256

// ---------------- scratch (device globals; no allocations allowed) ----------------
__device__ float g_u[KHOP * FF];
__device__ float g_v[KHOP * FF];
__device__ float g_s_src[KHOP * NN];
__device__ float g_s_dst[KHOP * NN];
__device__ float g_rowsum[KHOP * NN];
__device__ int   g_deg[KHOP * NN];
__device__ int   g_ptr[KHOP * NN];
__device__ int   g_fill[KHOP * NN];
__device__ int2  g_csr[(size_t)KHOP * EE + 32];      // (dst, w-as-int); +32 pad for warp over-read
__device__ __half g_Yh[(size_t)NN * FF];             // per-hop Y = X @ W_z (fp16, reused per hop)
__device__ __nv_bfloat16 g_Xhi[(size_t)NN * FF];
__device__ __nv_bfloat16 g_Xlo[(size_t)NN * FF];
__device__ __nv_bfloat16 g_Wthi[KHOP * FF * GN];     // transposed: [z][n][k]
__device__ __nv_bfloat16 g_Wtlo[KHOP * FF * GN];

__device__ __forceinline__ float elu1(float x) { return x > 0.f ? x : expm1f(x); }

// ---------------- small kernels (pipeline front) ----------------

__global__ void zero_kernel() {
    int i = blockIdx.x * blockDim.x + threadIdx.x;
    if (i < KHOP * NN) { g_deg[i] = 0; g_rowsum[i] = 0.f; }
}

__global__ void uv_kernel(const float* __restrict__ W, const float* __restrict__ a) {
    int z = blockIdx.x;
    int k = threadIdx.x;
    const float* wrow = W + (size_t)(z * FF + k) * GN;
    const float* au = a + z * 2 * FF;
    const float* av = au + FF;
    float u = 0.f, v = 0.f;
    #pragma unroll 8
    for (int j = 0; j < FF; j++) {
        float w = wrow[j];
        u = fmaf(w, au[j], u);
        v = fmaf(w, av[j], v);
    }
    g_u[z * FF + k] = u;
    g_v[z * FF + k] = v;
}

__global__ void __launch_bounds__(256) scores_kernel(const float* __restrict__ X) {
    __shared__ float su[KHOP][FF];
    __shared__ float sv[KHOP][FF];
    int tid = threadIdx.x;
    for (int i = tid; i < KHOP * FF; i += 256) {
        su[i / FF][i % FF] = g_u[i];
        sv[i / FF][i % FF] = g_v[i];
    }
    __syncthreads();
    int warp = tid >> 5, lane = tid & 31;
    int n = blockIdx.x * 8 + warp;
    if (n >= NN) return;
    float xr[8];
    #pragma unroll
    for (int j = 0; j < 8; j++) xr[j] = X[(size_t)n * FF + j * 32 + lane];
    #pragma unroll
    for (int z = 0; z < KHOP; z++) {
        float du = 0.f, dv = 0.f;
        #pragma unroll
        for (int j = 0; j < 8; j++) {
            du = fmaf(xr[j], su[z][j * 32 + lane], du);
            dv = fmaf(xr[j], sv[z][j * 32 + lane], dv);
        }
        #pragma unroll
        for (int off = 16; off > 0; off >>= 1) {
            du += __shfl_xor_sync(0xFFFFFFFFu, du, off);
            dv += __shfl_xor_sync(0xFFFFFFFFu, dv, off);
        }
        if (lane == 0) {
            g_s_src[z * NN + n] = du;
            g_s_dst[z * NN + n] = dv;
        }
    }
}

__global__ void hist_kernel(const int* __restrict__ kel) {
    int z = blockIdx.y;
    int e = blockIdx.x * 256 + threadIdx.x;
    if (e >= EE) return;
    int src = kel[(size_t)z * 2 * EE + e];
    atomicAdd(&g_deg[z * NN + src], 1);
}

__global__ void __launch_bounds__(1024) scan_kernel() {
    int z = blockIdx.x;
    __shared__ int wsum[32];
    int tid = threadIdx.x, lane = tid & 31, wid = tid >> 5;
    int carry = 0;
    for (int base = 0; base < NN; base += 1024) {
        int i = base + tid;
        int v = (i < NN) ? g_deg[z * NN + i] : 0;
        int x = v;
        #pragma unroll
        for (int off = 1; off < 32; off <<= 1) {
            int t = __shfl_up_sync(0xFFFFFFFFu, x, off);
            if (lane >= off) x += t;
        }
        if (lane == 31) wsum[wid] = x;
        __syncthreads();
        if (wid == 0) {
            int s = wsum[lane];
            #pragma unroll
            for (int off = 1; off < 32; off <<= 1) {
                int t = __shfl_up_sync(0xFFFFFFFFu, s, off);
                if (lane >= off) s += t;
            }
            wsum[lane] = s;
        }
        __syncthreads();
        int woff = wid ? wsum[wid - 1] : 0;
        int excl = carry + woff + x - v;
        if (i < NN) { g_ptr[z * NN + i] = excl; g_fill[z * NN + i] = excl; }
        int tot = wsum[31];
        __syncthreads();
        carry += tot;
    }
}

__global__ void build_kernel(const int* __restrict__ kel) {
    int z = blockIdx.y;
    int e = blockIdx.x * 256 + threadIdx.x;
    if (e >= EE) return;
    int src = kel[(size_t)z * 2 * EE + e];
    int dst = kel[(size_t)z * 2 * EE + EE + e];
    float sc = g_s_src[z * NN + src] + g_s_dst[z * NN + dst];
    float l = sc > 0.f ? sc : 0.2f * sc;           // leaky_relu(alpha=0.2)
    float w = expf(-l);
    int idx = atomicAdd(&g_fill[z * NN + src], 1);
    g_csr[(size_t)z * EE + idx] = make_int2(dst, __float_as_int(w));
    atomicAdd(&g_rowsum[z * NN + src], w);
}

// ---------------- bf16 split conversion ----------------

__device__ __forceinline__ uint32_t pkbf2(float a, float b) {
    __nv_bfloat162 t = __floats2bfloat162_rn(a, b);
    return *(uint32_t*)&t;
}
__device__ __forceinline__ uint32_t pkh2(float a, float b) {
    __half2 t = __floats2half2_rn(a, b);
    return *(uint32_t*)&t;
}

__global__ void __launch_bounds__(256) convX_kernel(const float* __restrict__ X) {
    size_t i = ((size_t)blockIdx.x * 256 + threadIdx.x) * 4;
    if (i >= (size_t)NN * FF) return;
    float4 v = *(const float4*)(X + i);
    float hx = __bfloat162float(__float2bfloat16_rn(v.x));
    float hy = __bfloat162float(__float2bfloat16_rn(v.y));
    float hz = __bfloat162float(__float2bfloat16_rn(v.z));
    float hw = __bfloat162float(__float2bfloat16_rn(v.w));
    uint2 hi = make_uint2(pkbf2(v.x, v.y), pkbf2(v.z, v.w));
    uint2 lo = make_uint2(pkbf2(v.x - hx, v.y - hy), pkbf2(v.z - hz, v.w - hw));
    *(uint2*)(g_Xhi + i) = hi;
    *(uint2*)(g_Xlo + i) = lo;
}

__global__ void __launch_bounds__(256) convW_kernel(const float* __restrict__ W) {
    int idx = blockIdx.x * 256 + threadIdx.x;
    if (idx >= KHOP * FF * GN) return;
    int z = idx >> 16;
    int rem = idx & 65535;
    int k = rem >> 8;
    int n = rem & 255;
    float w = W[(size_t)(z * FF + k) * GN + n];
    float hf = __bfloat162float(__float2bfloat16_rn(w));
    g_Wthi[z * 65536 + n * 256 + k] = __float2bfloat16_rn(w);
    g_Wtlo[z * 65536 + n * 256 + k] = __float2bfloat16_rn(w - hf);
}

// ---------------- mma.sync bf16 GEMM (base-ISA HMMA; sm_103-safe) ----------------
// Yh[128-tile, 128-tile] = X @ W_z via m16n8k16 row.col f32.bf16.bf16.f32
// hi/lo split: acc = Ahi*Bhi + Ahi*Blo + Alo*Bhi  (lo*lo dropped); fp16 output

#define SAW 40   // smem row pitch in bf16 (80 B: 16B-aligned, conflict-free frag reads)

__device__ __forceinline__ void mma16816(float* c, const uint32_t* a, const uint32_t* b) {
    asm volatile(
        "mma.sync.aligned.m16n8k16.row.col.f32.bf16.bf16.f32 "
        "{%0,%1,%2,%3}, {%4,%5,%6,%7}, {%8,%9}, {%0,%1,%2,%3};"
        : "+f"(c[0]), "+f"(c[1]), "+f"(c[2]), "+f"(c[3])
        : "r"(a[0]), "r"(a[1]), "r"(a[2]), "r"(a[3]), "r"(b[0]), "r"(b[1]));
}

__global__ void __launch_bounds__(256) gemm_mma_kernel(int z) {
    __shared__ __nv_bfloat16 sAhi[128 * SAW];
    __shared__ __nv_bfloat16 sAlo[128 * SAW];
    __shared__ __nv_bfloat16 sBhi[128 * SAW];
    __shared__ __nv_bfloat16 sBlo[128 * SAW];

    const int tid = threadIdx.x;
    const int wid = tid >> 5, lane = tid & 31;
    const int g = lane >> 2, tg = lane & 3;       // groupID, threadID-in-group
    const int warp_m = wid >> 2;                  // 0..1
    const int warp_n = wid & 3;                   // 0..3
    const int rowBase = blockIdx.x * 128;
    const int colBase = blockIdx.y * 128;

    const __nv_bfloat16* Wth = g_Wthi + (size_t)z * 65536;
    const __nv_bfloat16* Wtl = g_Wtlo + (size_t)z * 65536;

    float c[4][4][4];
    #pragma unroll
    for (int mt = 0; mt < 4; mt++)
        #pragma unroll
        for (int nt = 0; nt < 4; nt++)
            #pragma unroll
            for (int q = 0; q < 4; q++) c[mt][nt][q] = 0.f;

    for (int kc = 0; kc < 8; kc++) {
        const int k0g = kc * 32;
        #pragma unroll
        for (int it = 0; it < 2; it++) {
            int q = tid + it * 256;               // 0..511
            int r = q >> 2, s = q & 3;
            int row_g = rowBase + r;
            uint4 vh = make_uint4(0, 0, 0, 0), vl = make_uint4(0, 0, 0, 0);
            if (row_g < NN) {
                size_t go = (size_t)row_g * FF + k0g + s * 8;
                vh = *(const uint4*)(g_Xhi + go);
                vl = *(const uint4*)(g_Xlo + go);
            }
            *(uint4*)(sAhi + r * SAW + s * 8) = vh;
            *(uint4*)(sAlo + r * SAW + s * 8) = vl;
        }
        #pragma unroll
        for (int it = 0; it < 2; it++) {
            int q = tid + it * 256;
            int r = q >> 2, s = q & 3;            // n-row, k-seg
            size_t go = (size_t)(colBase + r) * 256 + k0g + s * 8;
            *(uint4*)(sBhi + r * SAW + s * 8) = *(const uint4*)(Wth + go);
            *(uint4*)(sBlo + r * SAW + s * 8) = *(const uint4*)(Wtl + go);
        }
        __syncthreads();

        #pragma unroll
        for (int ks = 0; ks < 2; ks++) {
            const int k0 = ks * 16;
            uint32_t ah[4][4], al[4][4];
            #pragma unroll
            for (int mt = 0; mt < 4; mt++) {
                int r0 = warp_m * 64 + mt * 16 + g;
                int kk = k0 + tg * 2;
                ah[mt][0] = *(const uint32_t*)(sAhi + r0 * SAW + kk);
                ah[mt][1] = *(const uint32_t*)(sAhi + (r0 + 8) * SAW + kk);
                ah[mt][2] = *(const uint32_t*)(sAhi + r0 * SAW + kk + 8);
                ah[mt][3] = *(const uint32_t*)(sAhi + (r0 + 8) * SAW + kk + 8);
                al[mt][0] = *(const uint32_t*)(sAlo + r0 * SAW + kk);
                al[mt][1] = *(const uint32_t*)(sAlo + (r0 + 8) * SAW + kk);
                al[mt][2] = *(const uint32_t*)(sAlo + r0 * SAW + kk + 8);
                al[mt][3] = *(const uint32_t*)(sAlo + (r0 + 8) * SAW + kk + 8);
            }
            uint32_t bh[4][2], bl[4][2];
            #pragma unroll
            for (int nt = 0; nt < 4; nt++) {
                int n0 = warp_n * 32 + nt * 8 + g;
                int kk = k0 + tg * 2;
                bh[nt][0] = *(const uint32_t*)(sBhi + n0 * SAW + kk);
                bh[nt][1] = *(const uint32_t*)(sBhi + n0 * SAW + kk + 8);
                bl[nt][0] = *(const uint32_t*)(sBlo + n0 * SAW + kk);
                bl[nt][1] = *(const uint32_t*)(sBlo + n0 * SAW + kk + 8);
            }
            #pragma unroll
            for (int mt = 0; mt < 4; mt++)
                #pragma unroll
                for (int nt = 0; nt < 4; nt++) {
                    mma16816(c[mt][nt], ah[mt], bh[nt]);
                    mma16816(c[mt][nt], ah[mt], bl[nt]);
                    mma16816(c[mt][nt], al[mt], bh[nt]);
                }
        }
        __syncthreads();
    }

    // epilogue: pack to fp16, 4-byte stores
    #pragma unroll
    for (int mt = 0; mt < 4; mt++) {
        int r0 = rowBase + warp_m * 64 + mt * 16 + g;
        #pragma unroll
        for (int nt = 0; nt < 4; nt++) {
            int col = colBase + warp_n * 32 + nt * 8 + tg * 2;
            if (r0 < NN)
                *(uint32_t*)(g_Yh + (size_t)r0 * GN + col) = pkh2(c[mt][nt][0], c[mt][nt][1]);
            if (r0 + 8 < NN)
                *(uint32_t*)(g_Yh + (size_t)(r0 + 8) * GN + col) = pkh2(c[mt][nt][2], c[mt][nt][3]);
        }
    }
}

// ---------------- per-hop aggregation: warp per node, accumulate through out ----------------
// val[n] = coef_z/rowsum_z(n) * sum_e w_e Yh[dst_e]
// mode 0: out = val ; mode 1: out += val ; mode 2: out = elu(out + val)
__global__ void __launch_bounds__(256) aggregate_kernel(int z, float coef, int mode,
                                                        float* __restrict__ out) {
    const int wid = threadIdx.x >> 5, lane = threadIdx.x & 31;
    const int n = blockIdx.x * 8 + wid;
    if (n >= NN) return;

    const int start = g_ptr[z * NN + n];
    const int d     = g_deg[z * NN + n];
    const int2* __restrict__ ce = g_csr + (size_t)z * EE + start;

    float acc[8];
    #pragma unroll
    for (int t = 0; t < 8; t++) acc[t] = 0.f;

    for (int base = 0; base < d; base += 32) {
        int cnt = min(32, d - base);
        int2 e = ce[base + lane];                // array-end pad makes over-read safe
        #pragma unroll 8
        for (int k = 0; k < cnt; k++) {
            int   dst = __shfl_sync(0xFFFFFFFFu, e.x, k);
            float w   = __int_as_float(__shfl_sync(0xFFFFFFFFu, e.y, k));
            uint4 v = *(const uint4*)(g_Yh + (size_t)dst * FF + lane * 8);
            float2 f0 = __half22float2(*(__half2*)&v.x);
            float2 f1 = __half22float2(*(__half2*)&v.y);
            float2 f2 = __half22float2(*(__half2*)&v.z);
            float2 f3 = __half22float2(*(__half2*)&v.w);
            acc[0] = fmaf(w, f0.x, acc[0]);
            acc[1] = fmaf(w, f0.y, acc[1]);
            acc[2] = fmaf(w, f1.x, acc[2]);
            acc[3] = fmaf(w, f1.y, acc[3]);
            acc[4] = fmaf(w, f2.x, acc[4]);
            acc[5] = fmaf(w, f2.y, acc[5]);
            acc[6] = fmaf(w, f3.x, acc[6]);
            acc[7] = fmaf(w, f3.y, acc[7]);
        }
    }

    float s = coef / g_rowsum[z * NN + n];
    float* dst = out + (size_t)n * FF + lane * 8;
    if (mode == 0) {
        *(float4*)dst       = make_float4(acc[0] * s, acc[1] * s, acc[2] * s, acc[3] * s);
        *(float4*)(dst + 4) = make_float4(acc[4] * s, acc[5] * s, acc[6] * s, acc[7] * s);
    } else {
        float4 p0 = *(float4*)dst;
        float4 p1 = *(float4*)(dst + 4);
        float r0 = fmaf(acc[0], s, p0.x), r1 = fmaf(acc[1], s, p0.y);
        float r2 = fmaf(acc[2], s, p0.z), r3 = fmaf(acc[3], s, p0.w);
        float r4 = fmaf(acc[4], s, p1.x), r5 = fmaf(acc[5], s, p1.y);
        float r6 = fmaf(acc[6], s, p1.z), r7 = fmaf(acc[7], s, p1.w);
        if (mode == 2) {
            r0 = elu1(r0); r1 = elu1(r1); r2 = elu1(r2); r3 = elu1(r3);
            r4 = elu1(r4); r5 = elu1(r5); r6 = elu1(r6); r7 = elu1(r7);
        }
        *(float4*)dst       = make_float4(r0, r1, r2, r3);
        *(float4*)(dst + 4) = make_float4(r4, r5, r6, r7);
    }
}

// ---------------- launch ----------------
extern "C" void kernel_launch(void* const* d_in, const int* in_sizes, int n_in,
                              void* d_out, int out_size) {
    const float* X   = (const float*)d_in[0];
    const int*   kel = (const int*)d_in[1];
    const float* W   = (const float*)d_in[2];
    const float* a   = (const float*)d_in[3];
    float* out = (float*)d_out;

    zero_kernel<<<(KHOP * NN + 255) / 256, 256>>>();
    uv_kernel<<<KHOP, 256>>>(W, a);
    scores_kernel<<<NN / 8, 256>>>(X);
    convX_kernel<<<(NN * FF / 4 + 255) / 256, 256>>>(X);
    convW_kernel<<<(KHOP * FF * GN + 255) / 256, 256>>>(W);
    hist_kernel<<<dim3(EE / 256, KHOP), 256>>>(kel);
    scan_kernel<<<KHOP, 1024>>>();
    build_kernel<<<dim3(EE / 256, KHOP), 256>>>(kel);

    const float coef[KHOP] = {0.5f, 0.25f, 0.125f};
    for (int z = 0; z < KHOP; z++) {
        gemm_mma_kernel<<<dim3((NN + 127) / 128, GN / 128), 256>>>(z);
        aggregate_kernel<<<(NN + 7) / 8, 256>>>(z, coef[z], (z == KHOP - 1) ? 2 : (z == 0 ? 0 : 1), out);
    }
}

// round 9
// speedup vs baseline: 1.7929x; 1.7929x over previous
#include <cuda_runtime.h>
#include <cuda_bf16.h>
#include <cuda_fp16.h>
#include <math.h>
#include <stdint.h>

#define NN 50000
#define EE 1600000
#define FF 256
#define KHOP 3
#define GN 256

// ---------------- scratch (device globals; no allocations allowed) ----------------
__device__ float g_u[KHOP * FF];
__device__ float g_v[KHOP * FF];
__device__ float g_s_src[KHOP * NN];
__device__ float g_s_dst[KHOP * NN];
__device__ float g_rowsum[KHOP * NN];
__device__ int   g_deg[KHOP * NN];
__device__ int   g_ptr[KHOP * NN];
__device__ int   g_fill[KHOP * NN];
__device__ int2  g_csr[(size_t)KHOP * EE + 32];      // (dst, w-as-int); +32 pad for warp over-read
__device__ __half g_Yh[(size_t)KHOP * NN * FF];      // Y_z = X @ W_z, fp16
__device__ __half g_Xh[(size_t)NN * FF];             // X in fp16
__device__ __half g_Wth[KHOP * FF * GN];             // W transposed [z][n][k], fp16

__device__ __forceinline__ float elu1(float x) { return x > 0.f ? x : expm1f(x); }

// ---------------- small kernels (pipeline front) ----------------

__global__ void zero_kernel() {
    int i = blockIdx.x * blockDim.x + threadIdx.x;
    if (i < KHOP * NN) { g_deg[i] = 0; g_rowsum[i] = 0.f; }
}

__global__ void uv_kernel(const float* __restrict__ W, const float* __restrict__ a) {
    int z = blockIdx.x;
    int k = threadIdx.x;
    const float* wrow = W + (size_t)(z * FF + k) * GN;
    const float* au = a + z * 2 * FF;
    const float* av = au + FF;
    float u = 0.f, v = 0.f;
    #pragma unroll 8
    for (int j = 0; j < FF; j++) {
        float w = wrow[j];
        u = fmaf(w, au[j], u);
        v = fmaf(w, av[j], v);
    }
    g_u[z * FF + k] = u;
    g_v[z * FF + k] = v;
}

__global__ void __launch_bounds__(256) scores_kernel(const float* __restrict__ X) {
    __shared__ float su[KHOP][FF];
    __shared__ float sv[KHOP][FF];
    int tid = threadIdx.x;
    for (int i = tid; i < KHOP * FF; i += 256) {
        su[i / FF][i % FF] = g_u[i];
        sv[i / FF][i % FF] = g_v[i];
    }
    __syncthreads();
    int warp = tid >> 5, lane = tid & 31;
    int n = blockIdx.x * 8 + warp;
    if (n >= NN) return;
    float xr[8];
    #pragma unroll
    for (int j = 0; j < 8; j++) xr[j] = X[(size_t)n * FF + j * 32 + lane];
    #pragma unroll
    for (int z = 0; z < KHOP; z++) {
        float du = 0.f, dv = 0.f;
        #pragma unroll
        for (int j = 0; j < 8; j++) {
            du = fmaf(xr[j], su[z][j * 32 + lane], du);
            dv = fmaf(xr[j], sv[z][j * 32 + lane], dv);
        }
        #pragma unroll
        for (int off = 16; off > 0; off >>= 1) {
            du += __shfl_xor_sync(0xFFFFFFFFu, du, off);
            dv += __shfl_xor_sync(0xFFFFFFFFu, dv, off);
        }
        if (lane == 0) {
            g_s_src[z * NN + n] = du;
            g_s_dst[z * NN + n] = dv;
        }
    }
}

__global__ void hist_kernel(const int* __restrict__ kel) {
    int z = blockIdx.y;
    int e = blockIdx.x * 256 + threadIdx.x;
    if (e >= EE) return;
    int src = kel[(size_t)z * 2 * EE + e];
    atomicAdd(&g_deg[z * NN + src], 1);
}

__global__ void __launch_bounds__(1024) scan_kernel() {
    int z = blockIdx.x;
    __shared__ int wsum[32];
    int tid = threadIdx.x, lane = tid & 31, wid = tid >> 5;
    int carry = 0;
    for (int base = 0; base < NN; base += 1024) {
        int i = base + tid;
        int v = (i < NN) ? g_deg[z * NN + i] : 0;
        int x = v;
        #pragma unroll
        for (int off = 1; off < 32; off <<= 1) {
            int t = __shfl_up_sync(0xFFFFFFFFu, x, off);
            if (lane >= off) x += t;
        }
        if (lane == 31) wsum[wid] = x;
        __syncthreads();
        if (wid == 0) {
            int s = wsum[lane];
            #pragma unroll
            for (int off = 1; off < 32; off <<= 1) {
                int t = __shfl_up_sync(0xFFFFFFFFu, s, off);
                if (lane >= off) s += t;
            }
            wsum[lane] = s;
        }
        __syncthreads();
        int woff = wid ? wsum[wid - 1] : 0;
        int excl = carry + woff + x - v;
        if (i < NN) { g_ptr[z * NN + i] = excl; g_fill[z * NN + i] = excl; }
        int tot = wsum[31];
        __syncthreads();
        carry += tot;
    }
}

__global__ void build_kernel(const int* __restrict__ kel) {
    int z = blockIdx.y;
    int e = blockIdx.x * 256 + threadIdx.x;
    if (e >= EE) return;
    int src = kel[(size_t)z * 2 * EE + e];
    int dst = kel[(size_t)z * 2 * EE + EE + e];
    float sc = g_s_src[z * NN + src] + g_s_dst[z * NN + dst];
    float l = sc > 0.f ? sc : 0.2f * sc;           // leaky_relu(alpha=0.2)
    float w = expf(-l);
    int idx = atomicAdd(&g_fill[z * NN + src], 1);
    g_csr[(size_t)z * EE + idx] = make_int2(dst, __float_as_int(w));
    atomicAdd(&g_rowsum[z * NN + src], w);
}

// ---------------- fp16 conversions ----------------

__device__ __forceinline__ uint32_t pkh2(float a, float b) {
    __half2 t = __floats2half2_rn(a, b);
    return *(uint32_t*)&t;
}

__global__ void __launch_bounds__(256) convX_kernel(const float* __restrict__ X) {
    size_t i = ((size_t)blockIdx.x * 256 + threadIdx.x) * 4;
    if (i >= (size_t)NN * FF) return;
    float4 v = *(const float4*)(X + i);
    *(uint2*)(g_Xh + i) = make_uint2(pkh2(v.x, v.y), pkh2(v.z, v.w));
}

__global__ void __launch_bounds__(256) convW_kernel(const float* __restrict__ W) {
    int idx = blockIdx.x * 256 + threadIdx.x;
    if (idx >= KHOP * FF * GN) return;
    int z = idx >> 16;
    int rem = idx & 65535;
    int k = rem >> 8;
    int n = rem & 255;
    float w = W[(size_t)(z * FF + k) * GN + n];
    g_Wth[z * 65536 + n * 256 + k] = __float2half_rn(w);
}

// ---------------- mma.sync fp16 GEMM (base-ISA HMMA; sm_103-safe) ----------------
// Yh_z[128-tile, 128-tile] = Xh @ Wh_z via m16n8k16 row.col f32.f16.f16.f32 (single pass)

#define SAW 40   // smem row pitch in halfs (80 B: 16B-aligned, conflict-free frag reads)

__device__ __forceinline__ void mma16816h(float* c, const uint32_t* a, const uint32_t* b) {
    asm volatile(
        "mma.sync.aligned.m16n8k16.row.col.f32.f16.f16.f32 "
        "{%0,%1,%2,%3}, {%4,%5,%6,%7}, {%8,%9}, {%0,%1,%2,%3};"
        : "+f"(c[0]), "+f"(c[1]), "+f"(c[2]), "+f"(c[3])
        : "r"(a[0]), "r"(a[1]), "r"(a[2]), "r"(a[3]), "r"(b[0]), "r"(b[1]));
}

__global__ void __launch_bounds__(256) gemm_mma_kernel() {
    __shared__ __half sA[128 * SAW];
    __shared__ __half sB[128 * SAW];

    const int tid = threadIdx.x;
    const int wid = tid >> 5, lane = tid & 31;
    const int g = lane >> 2, tg = lane & 3;       // groupID, threadID-in-group
    const int warp_m = wid >> 2;                  // 0..1
    const int warp_n = wid & 3;                   // 0..3
    const int rowBase = blockIdx.x * 128;
    const int colBase = blockIdx.y * 128;
    const int z = blockIdx.z;

    const __half* Wth = g_Wth + (size_t)z * 65536;
    __half* Yh = g_Yh + (size_t)z * NN * FF;

    float c[4][4][4];
    #pragma unroll
    for (int mt = 0; mt < 4; mt++)
        #pragma unroll
        for (int nt = 0; nt < 4; nt++)
            #pragma unroll
            for (int q = 0; q < 4; q++) c[mt][nt][q] = 0.f;

    for (int kc = 0; kc < 8; kc++) {
        const int k0g = kc * 32;
        // A tile: 128 rows x 32 halfs = 512 uint4; 2 per thread
        #pragma unroll
        for (int it = 0; it < 2; it++) {
            int q = tid + it * 256;               // 0..511
            int r = q >> 2, s = q & 3;
            int row_g = rowBase + r;
            uint4 va = make_uint4(0, 0, 0, 0);
            if (row_g < NN) va = *(const uint4*)(g_Xh + (size_t)row_g * FF + k0g + s * 8);
            *(uint4*)(sA + r * SAW + s * 8) = va;
        }
        // B tile: 128 n-rows x 32 k halfs
        #pragma unroll
        for (int it = 0; it < 2; it++) {
            int q = tid + it * 256;
            int r = q >> 2, s = q & 3;
            *(uint4*)(sB + r * SAW + s * 8) =
                *(const uint4*)(Wth + (size_t)(colBase + r) * 256 + k0g + s * 8);
        }
        __syncthreads();

        #pragma unroll
        for (int ks = 0; ks < 2; ks++) {
            const int k0 = ks * 16;
            uint32_t ah[4][4];
            #pragma unroll
            for (int mt = 0; mt < 4; mt++) {
                int r0 = warp_m * 64 + mt * 16 + g;
                int kk = k0 + tg * 2;
                ah[mt][0] = *(const uint32_t*)(sA + r0 * SAW + kk);
                ah[mt][1] = *(const uint32_t*)(sA + (r0 + 8) * SAW + kk);
                ah[mt][2] = *(const uint32_t*)(sA + r0 * SAW + kk + 8);
                ah[mt][3] = *(const uint32_t*)(sA + (r0 + 8) * SAW + kk + 8);
            }
            uint32_t bh[4][2];
            #pragma unroll
            for (int nt = 0; nt < 4; nt++) {
                int n0 = warp_n * 32 + nt * 8 + g;
                int kk = k0 + tg * 2;
                bh[nt][0] = *(const uint32_t*)(sB + n0 * SAW + kk);
                bh[nt][1] = *(const uint32_t*)(sB + n0 * SAW + kk + 8);
            }
            #pragma unroll
            for (int mt = 0; mt < 4; mt++)
                #pragma unroll
                for (int nt = 0; nt < 4; nt++)
                    mma16816h(c[mt][nt], ah[mt], bh[nt]);
        }
        __syncthreads();
    }

    // epilogue: pack to fp16, 4-byte stores
    #pragma unroll
    for (int mt = 0; mt < 4; mt++) {
        int r0 = rowBase + warp_m * 64 + mt * 16 + g;
        #pragma unroll
        for (int nt = 0; nt < 4; nt++) {
            int col = colBase + warp_n * 32 + nt * 8 + tg * 2;
            if (r0 < NN)
                *(uint32_t*)(Yh + (size_t)r0 * GN + col) = pkh2(c[mt][nt][0], c[mt][nt][1]);
            if (r0 + 8 < NN)
                *(uint32_t*)(Yh + (size_t)(r0 + 8) * GN + col) = pkh2(c[mt][nt][2], c[mt][nt][3]);
        }
    }
}

// ---------------- fused 3-hop aggregation, feature-split into 2 passes ----------------
// pass p covers features [p*128, (p+1)*128); warp per node, lane holds 4 features.
// Per-pass Y working set = 3 x 12.8 MB -> L2-resident re-use.
__global__ void __launch_bounds__(256) aggregate_fused_kernel(float* __restrict__ out) {
    const int wid = threadIdx.x >> 5, lane = threadIdx.x & 31;
    const int n = blockIdx.x * 8 + wid;
    const int p = blockIdx.y;                    // feature half
    if (n >= NN) return;
    const int fo = p * 128 + lane * 4;

    float tot[4] = {0.f, 0.f, 0.f, 0.f};

    #pragma unroll
    for (int z = 0; z < KHOP; z++) {
        const int start = g_ptr[z * NN + n];
        const int d     = g_deg[z * NN + n];
        const int2* __restrict__ ce = g_csr + (size_t)z * EE + start;
        const __half* __restrict__ Yz = g_Yh + (size_t)z * NN * FF + fo;

        float acc[4] = {0.f, 0.f, 0.f, 0.f};

        for (int base = 0; base < d; base += 32) {
            int cnt = min(32, d - base);
            int2 e = ce[base + lane];            // array-end pad makes over-read safe
            #pragma unroll 8
            for (int k = 0; k < cnt; k++) {
                int   dst = __shfl_sync(0xFFFFFFFFu, e.x, k);
                float w   = __int_as_float(__shfl_sync(0xFFFFFFFFu, e.y, k));
                uint2 v = *(const uint2*)(Yz + (size_t)dst * FF);
                float2 f0 = __half22float2(*(__half2*)&v.x);
                float2 f1 = __half22float2(*(__half2*)&v.y);
                acc[0] = fmaf(w, f0.x, acc[0]);
                acc[1] = fmaf(w, f0.y, acc[1]);
                acc[2] = fmaf(w, f1.x, acc[2]);
                acc[3] = fmaf(w, f1.y, acc[3]);
            }
        }
        const float coef = (z == 0) ? 0.5f : (z == 1) ? 0.25f : 0.125f;
        float s = coef / g_rowsum[z * NN + n];
        #pragma unroll
        for (int t = 0; t < 4; t++) tot[t] = fmaf(acc[t], s, tot[t]);
    }

    *(float4*)(out + (size_t)n * FF + fo) =
        make_float4(elu1(tot[0]), elu1(tot[1]), elu1(tot[2]), elu1(tot[3]));
}

// ---------------- launch ----------------
extern "C" void kernel_launch(void* const* d_in, const int* in_sizes, int n_in,
                              void* d_out, int out_size) {
    const float* X   = (const float*)d_in[0];
    const int*   kel = (const int*)d_in[1];
    const float* W   = (const float*)d_in[2];
    const float* a   = (const float*)d_in[3];
    float* out = (float*)d_out;

    // order chosen so ncu (-s 5 -c 1) captures gemm_mma_kernel (6th launch)
    zero_kernel<<<(KHOP * NN + 255) / 256, 256>>>();                 // 1
    uv_kernel<<<KHOP, 256>>>(W, a);                                  // 2
    convX_kernel<<<(NN * FF / 4 + 255) / 256, 256>>>(X);             // 3
    convW_kernel<<<(KHOP * FF * GN + 255) / 256, 256>>>(W);          // 4
    scores_kernel<<<NN / 8, 256>>>(X);                               // 5
    gemm_mma_kernel<<<dim3((NN + 127) / 128, GN / 128, KHOP), 256>>>(); // 6 (profiled)
    hist_kernel<<<dim3(EE / 256, KHOP), 256>>>(kel);                 // 7
    scan_kernel<<<KHOP, 1024>>>();                                   // 8
    build_kernel<<<dim3(EE / 256, KHOP), 256>>>(kel);                // 9
    aggregate_fused_kernel<<<dim3((NN + 7) / 8, 2), 256>>>(out);     // 10
}

// round 11
// speedup vs baseline: 1.8952x; 1.0571x over previous
#include <cuda_runtime.h>
#include <cuda_bf16.h>
#include <cuda_fp16.h>
#include <math.h>
#include <stdint.h>

#define NN 50000
#define EE 1600000
#define FF 256
#define KHOP 3
#define GN 256
#define TOTN (KHOP * NN)          // 150000
#define SCAN_BLOCKS ((TOTN + 1023) / 1024)   // 147

// ---------------- scratch (device globals; no allocations allowed) ----------------
__device__ float g_u[KHOP * FF];
__device__ float g_v[KHOP * FF];
__device__ float g_s_src[KHOP * NN];
__device__ float g_s_dst[KHOP * NN];
__device__ float g_rowsum[KHOP * NN];
__device__ int   g_deg[KHOP * NN];
__device__ int   g_ptr[KHOP * NN];
__device__ int   g_fill[KHOP * NN];
__device__ int   g_bsum[SCAN_BLOCKS];
__device__ int   g_boff[SCAN_BLOCKS];
__device__ int2  g_csr[(size_t)KHOP * EE + 32];      // (dst, w-as-int); +32 pad for warp over-read
__device__ __half g_Yh[(size_t)KHOP * NN * FF];      // Y_z = X @ W_z, fp16
__device__ __half g_Xh[(size_t)NN * FF];             // X in fp16
__device__ __half g_Wth[KHOP * FF * GN];             // W transposed [z][n][k], fp16

__device__ __forceinline__ float elu1(float x) { return x > 0.f ? x : expm1f(x); }

// ---------------- small kernels (pipeline front) ----------------

__global__ void zero_kernel() {
    int i = blockIdx.x * blockDim.x + threadIdx.x;
    if (i < TOTN) { g_deg[i] = 0; g_rowsum[i] = 0.f; }
}

__global__ void uv_kernel(const float* __restrict__ W, const float* __restrict__ a) {
    int z = blockIdx.x;
    int k = threadIdx.x;
    const float* wrow = W + (size_t)(z * FF + k) * GN;
    const float* au = a + z * 2 * FF;
    const float* av = au + FF;
    float u = 0.f, v = 0.f;
    #pragma unroll 8
    for (int j = 0; j < FF; j++) {
        float w = wrow[j];
        u = fmaf(w, au[j], u);
        v = fmaf(w, av[j], v);
    }
    g_u[z * FF + k] = u;
    g_v[z * FF + k] = v;
}

__global__ void __launch_bounds__(256) scores_kernel(const float* __restrict__ X) {
    __shared__ float su[KHOP][FF];
    __shared__ float sv[KHOP][FF];
    int tid = threadIdx.x;
    for (int i = tid; i < KHOP * FF; i += 256) {
        su[i / FF][i % FF] = g_u[i];
        sv[i / FF][i % FF] = g_v[i];
    }
    __syncthreads();
    int warp = tid >> 5, lane = tid & 31;
    int n = blockIdx.x * 8 + warp;
    if (n >= NN) return;
    float xr[8];
    #pragma unroll
    for (int j = 0; j < 8; j++) xr[j] = X[(size_t)n * FF + j * 32 + lane];
    #pragma unroll
    for (int z = 0; z < KHOP; z++) {
        float du = 0.f, dv = 0.f;
        #pragma unroll
        for (int j = 0; j < 8; j++) {
            du = fmaf(xr[j], su[z][j * 32 + lane], du);
            dv = fmaf(xr[j], sv[z][j * 32 + lane], dv);
        }
        #pragma unroll
        for (int off = 16; off > 0; off >>= 1) {
            du += __shfl_xor_sync(0xFFFFFFFFu, du, off);
            dv += __shfl_xor_sync(0xFFFFFFFFu, dv, off);
        }
        if (lane == 0) {
            g_s_src[z * NN + n] = du;
            g_s_dst[z * NN + n] = dv;
        }
    }
}

// 4 edges per thread via int4 (EE divisible by 4; grid covers all EE/4 vectors)
__global__ void hist_kernel(const int* __restrict__ kel) {
    int z = blockIdx.y;
    int e = (blockIdx.x * 256 + threadIdx.x) * 4;
    if (e >= EE) return;
    int4 s = __ldcs((const int4*)(kel + (size_t)z * 2 * EE + e));
    atomicAdd(&g_deg[z * NN + s.x], 1);
    atomicAdd(&g_deg[z * NN + s.y], 1);
    atomicAdd(&g_deg[z * NN + s.z], 1);
    atomicAdd(&g_deg[z * NN + s.w], 1);
}

// ---- 3-phase parallel scan over the whole 150K degree array ----
// hop boundaries contribute exactly z*EE, so per-hop ptr = global_scan[i] - z*EE.
__global__ void __launch_bounds__(1024) scanA_kernel() {
    __shared__ int wsum[32];
    int b = blockIdx.x, tid = threadIdx.x, lane = tid & 31, wid = tid >> 5;
    int i = b * 1024 + tid;
    int v = (i < TOTN) ? g_deg[i] : 0;
    int x = v;
    #pragma unroll
    for (int off = 1; off < 32; off <<= 1) {
        int t = __shfl_up_sync(0xFFFFFFFFu, x, off);
        if (lane >= off) x += t;
    }
    if (lane == 31) wsum[wid] = x;
    __syncthreads();
    if (wid == 0) {
        int s = wsum[lane];
        #pragma unroll
        for (int off = 1; off < 32; off <<= 1) {
            int t = __shfl_up_sync(0xFFFFFFFFu, s, off);
            if (lane >= off) s += t;
        }
        wsum[lane] = s;
    }
    __syncthreads();
    int woff = wid ? wsum[wid - 1] : 0;
    if (i < TOTN) g_ptr[i] = woff + x - v;        // local exclusive
    if (tid == 1023) g_bsum[b] = wsum[31];
}

__global__ void __launch_bounds__(256) scanB_kernel() {
    __shared__ int wsum[8];
    int tid = threadIdx.x, lane = tid & 31, wid = tid >> 5;
    int v = (tid < SCAN_BLOCKS) ? g_bsum[tid] : 0;
    int x = v;
    #pragma unroll
    for (int off = 1; off < 32; off <<= 1) {
        int t = __shfl_up_sync(0xFFFFFFFFu, x, off);
        if (lane >= off) x += t;
    }
    if (lane == 31) wsum[wid] = x;
    __syncthreads();
    if (wid == 0 && lane < 8) {
        int s = wsum[lane];
        #pragma unroll
        for (int off = 1; off < 8; off <<= 1) {
            int t = __shfl_up_sync(0xFFu, s, off);
            if (lane >= off) s += t;
        }
        wsum[lane] = s;
    }
    __syncthreads();
    int woff = wid ? wsum[wid - 1] : 0;
    if (tid < SCAN_BLOCKS) g_boff[tid] = woff + x - v;   // exclusive block offsets
}

__global__ void __launch_bounds__(1024) scanC_kernel() {
    int b = blockIdx.x;
    int i = b * 1024 + threadIdx.x;
    if (i >= TOTN) return;
    int z = (i >= 2 * NN) ? 2 : (i >= NN) ? 1 : 0;
    int val = g_ptr[i] + g_boff[b] - z * EE;
    g_ptr[i] = val;
    g_fill[i] = val;
}

__global__ void build_kernel(const int* __restrict__ kel) {
    int z = blockIdx.y;
    int e = blockIdx.x * 256 + threadIdx.x;
    if (e >= EE) return;
    int src = __ldcs(kel + (size_t)z * 2 * EE + e);
    int dst = __ldcs(kel + (size_t)z * 2 * EE + EE + e);
    float sc = g_s_src[z * NN + src] + g_s_dst[z * NN + dst];
    float l = sc > 0.f ? sc : 0.2f * sc;           // leaky_relu(alpha=0.2)
    float w = expf(-l);
    int idx = atomicAdd(&g_fill[z * NN + src], 1);
    __stcs(&g_csr[(size_t)z * EE + idx], make_int2(dst, __float_as_int(w)));
    atomicAdd(&g_rowsum[z * NN + src], w);
}

// ---------------- fp16 conversions ----------------

__device__ __forceinline__ uint32_t pkh2(float a, float b) {
    __half2 t = __floats2half2_rn(a, b);
    return *(uint32_t*)&t;
}

__global__ void __launch_bounds__(256) convX_kernel(const float* __restrict__ X) {
    size_t i = ((size_t)blockIdx.x * 256 + threadIdx.x) * 4;
    if (i >= (size_t)NN * FF) return;
    float4 v = *(const float4*)(X + i);
    *(uint2*)(g_Xh + i) = make_uint2(pkh2(v.x, v.y), pkh2(v.z, v.w));
}

__global__ void __launch_bounds__(256) convW_kernel(const float* __restrict__ W) {
    int idx = blockIdx.x * 256 + threadIdx.x;
    if (idx >= KHOP * FF * GN) return;
    int z = idx >> 16;
    int rem = idx & 65535;
    int k = rem >> 8;
    int n = rem & 255;
    float w = W[(size_t)(z * FF + k) * GN + n];
    g_Wth[z * 65536 + n * 256 + k] = __float2half_rn(w);
}

// ---------------- mma.sync fp16 GEMM (base-ISA HMMA; sm_103-safe) ----------------

#define SAW 40   // smem row pitch in halfs (80 B: 16B-aligned, conflict-free frag reads)

__device__ __forceinline__ void mma16816h(float* c, const uint32_t* a, const uint32_t* b) {
    asm volatile(
        "mma.sync.aligned.m16n8k16.row.col.f32.f16.f16.f32 "
        "{%0,%1,%2,%3}, {%4,%5,%6,%7}, {%8,%9}, {%0,%1,%2,%3};"
        : "+f"(c[0]), "+f"(c[1]), "+f"(c[2]), "+f"(c[3])
        : "r"(a[0]), "r"(a[1]), "r"(a[2]), "r"(a[3]), "r"(b[0]), "r"(b[1]));
}

__global__ void __launch_bounds__(256) gemm_mma_kernel() {
    __shared__ __half sA[128 * SAW];
    __shared__ __half sB[128 * SAW];

    const int tid = threadIdx.x;
    const int wid = tid >> 5, lane = tid & 31;
    const int g = lane >> 2, tg = lane & 3;
    const int warp_m = wid >> 2;
    const int warp_n = wid & 3;
    const int rowBase = blockIdx.x * 128;
    const int colBase = blockIdx.y * 128;
    const int z = blockIdx.z;

    const __half* Wth = g_Wth + (size_t)z * 65536;
    __half* Yh = g_Yh + (size_t)z * NN * FF;

    float c[4][4][4];
    #pragma unroll
    for (int mt = 0; mt < 4; mt++)
        #pragma unroll
        for (int nt = 0; nt < 4; nt++)
            #pragma unroll
            for (int q = 0; q < 4; q++) c[mt][nt][q] = 0.f;

    for (int kc = 0; kc < 8; kc++) {
        const int k0g = kc * 32;
        #pragma unroll
        for (int it = 0; it < 2; it++) {
            int q = tid + it * 256;
            int r = q >> 2, s = q & 3;
            int row_g = rowBase + r;
            uint4 va = make_uint4(0, 0, 0, 0);
            if (row_g < NN) va = *(const uint4*)(g_Xh + (size_t)row_g * FF + k0g + s * 8);
            *(uint4*)(sA + r * SAW + s * 8) = va;
        }
        #pragma unroll
        for (int it = 0; it < 2; it++) {
            int q = tid + it * 256;
            int r = q >> 2, s = q & 3;
            *(uint4*)(sB + r * SAW + s * 8) =
                *(const uint4*)(Wth + (size_t)(colBase + r) * 256 + k0g + s * 8);
        }
        __syncthreads();

        #pragma unroll
        for (int ks = 0; ks < 2; ks++) {
            const int k0 = ks * 16;
            uint32_t ah[4][4];
            #pragma unroll
            for (int mt = 0; mt < 4; mt++) {
                int r0 = warp_m * 64 + mt * 16 + g;
                int kk = k0 + tg * 2;
                ah[mt][0] = *(const uint32_t*)(sA + r0 * SAW + kk);
                ah[mt][1] = *(const uint32_t*)(sA + (r0 + 8) * SAW + kk);
                ah[mt][2] = *(const uint32_t*)(sA + r0 * SAW + kk + 8);
                ah[mt][3] = *(const uint32_t*)(sA + (r0 + 8) * SAW + kk + 8);
            }
            uint32_t bh[4][2];
            #pragma unroll
            for (int nt = 0; nt < 4; nt++) {
                int n0 = warp_n * 32 + nt * 8 + g;
                int kk = k0 + tg * 2;
                bh[nt][0] = *(const uint32_t*)(sB + n0 * SAW + kk);
                bh[nt][1] = *(const uint32_t*)(sB + n0 * SAW + kk + 8);
            }
            #pragma unroll
            for (int mt = 0; mt < 4; mt++)
                #pragma unroll
                for (int nt = 0; nt < 4; nt++)
                    mma16816h(c[mt][nt], ah[mt], bh[nt]);
        }
        __syncthreads();
    }

    #pragma unroll
    for (int mt = 0; mt < 4; mt++) {
        int r0 = rowBase + warp_m * 64 + mt * 16 + g;
        #pragma unroll
        for (int nt = 0; nt < 4; nt++) {
            int col = colBase + warp_n * 32 + nt * 8 + tg * 2;
            if (r0 < NN)
                *(uint32_t*)(Yh + (size_t)r0 * GN + col) = pkh2(c[mt][nt][0], c[mt][nt][1]);
            if (r0 + 8 < NN)
                *(uint32_t*)(Yh + (size_t)(r0 + 8) * GN + col) = pkh2(c[mt][nt][2], c[mt][nt][3]);
        }
    }
}

// ---------------- fused 3-hop aggregation, feature-split into 2 passes ----------------
__global__ void __launch_bounds__(256) aggregate_fused_kernel(float* __restrict__ out) {
    const int wid = threadIdx.x >> 5, lane = threadIdx.x & 31;
    const int n = blockIdx.x * 8 + wid;
    const int p = blockIdx.y;                    // feature half
    if (n >= NN) return;
    const int fo = p * 128 + lane * 4;

    float tot[4] = {0.f, 0.f, 0.f, 0.f};

    #pragma unroll
    for (int z = 0; z < KHOP; z++) {
        const int start = g_ptr[z * NN + n];
        const int d     = g_deg[z * NN + n];
        const int2* __restrict__ ce = g_csr + (size_t)z * EE + start;
        const __half* __restrict__ Yz = g_Yh + (size_t)z * NN * FF + fo;

        float acc[4] = {0.f, 0.f, 0.f, 0.f};

        for (int base = 0; base < d; base += 32) {
            int cnt = min(32, d - base);
            int2 e = __ldcs(&ce[base + lane]);   // streaming: don't evict hot Y
            #pragma unroll 8
            for (int k = 0; k < cnt; k++) {
                int   dst = __shfl_sync(0xFFFFFFFFu, e.x, k);
                float w   = __int_as_float(__shfl_sync(0xFFFFFFFFu, e.y, k));
                uint2 v = *(const uint2*)(Yz + (size_t)dst * FF);
                float2 f0 = __half22float2(*(__half2*)&v.x);
                float2 f1 = __half22float2(*(__half2*)&v.y);
                acc[0] = fmaf(w, f0.x, acc[0]);
                acc[1] = fmaf(w, f0.y, acc[1]);
                acc[2] = fmaf(w, f1.x, acc[2]);
                acc[3] = fmaf(w, f1.y, acc[3]);
            }
        }
        const float coef = (z == 0) ? 0.5f : (z == 1) ? 0.25f : 0.125f;
        float s = coef / g_rowsum[z * NN + n];
        #pragma unroll
        for (int t = 0; t < 4; t++) tot[t] = fmaf(acc[t], s, tot[t]);
    }

    float4 o = make_float4(elu1(tot[0]), elu1(tot[1]), elu1(tot[2]), elu1(tot[3]));
    __stcs((float4*)(out + (size_t)n * FF + fo), o);
}

// ---------------- launch ----------------
extern "C" void kernel_launch(void* const* d_in, const int* in_sizes, int n_in,
                              void* d_out, int out_size) {
    const float* X   = (const float*)d_in[0];
    const int*   kel = (const int*)d_in[1];
    const float* W   = (const float*)d_in[2];
    const float* a   = (const float*)d_in[3];
    float* out = (float*)d_out;

    zero_kernel<<<(TOTN + 255) / 256, 256>>>();
    uv_kernel<<<KHOP, 256>>>(W, a);
    convX_kernel<<<(NN * FF / 4 + 255) / 256, 256>>>(X);
    convW_kernel<<<(KHOP * FF * GN + 255) / 256, 256>>>(W);
    scores_kernel<<<NN / 8, 256>>>(X);
    gemm_mma_kernel<<<dim3((NN + 127) / 128, GN / 128, KHOP), 256>>>();
    hist_kernel<<<dim3((EE / 4 + 255) / 256, KHOP), 256>>>(kel);   // FIX: full edge coverage (1563 blocks)
    scanA_kernel<<<SCAN_BLOCKS, 1024>>>();
    scanB_kernel<<<1, 256>>>();
    scanC_kernel<<<SCAN_BLOCKS, 1024>>>();
    build_kernel<<<dim3(EE / 256, KHOP), 256>>>(kel);
    aggregate_fused_kernel<<<dim3((NN + 7) / 8, 2), 256>>>(out);
}

// round 12
// speedup vs baseline: 2.0108x; 1.0610x over previous
#include <cuda_runtime.h>
#include <cuda_bf16.h>
#include <cuda_fp16.h>
#include <math.h>
#include <stdint.h>

#define NN 50000
#define EE 1600000
#define FF 256
#define KHOP 3
#define GN 256
#define TOTN (KHOP * NN)          // 150000
#define SCAN_BLOCKS ((TOTN + 1023) / 1024)   // 147

// ---------------- scratch (device globals; no allocations allowed) ----------------
__device__ float g_u[KHOP * FF];
__device__ float g_v[KHOP * FF];
__device__ float g_s_src[KHOP * NN];
__device__ float g_s_dst[KHOP * NN];
__device__ int   g_deg[KHOP * NN];
__device__ int   g_ptr[KHOP * NN];
__device__ int   g_fill[KHOP * NN];
__device__ int   g_bsum[SCAN_BLOCKS];
__device__ int   g_boff[SCAN_BLOCKS];
__device__ int2  g_csr[(size_t)KHOP * EE + 32];      // (dst, w-as-int); +32 pad for warp over-read
__device__ __half g_Yh[(size_t)KHOP * NN * FF];      // Y_z = X @ W_z, fp16
__device__ __half g_Xh[(size_t)NN * FF];             // X in fp16
__device__ __half g_Wth[KHOP * FF * GN];             // W transposed [z][n][k], fp16

__device__ __forceinline__ float elu1(float x) { return x > 0.f ? x : expm1f(x); }

// ---------------- small kernels (pipeline front) ----------------

__global__ void zero_kernel() {
    int i = blockIdx.x * blockDim.x + threadIdx.x;
    if (i < TOTN) g_deg[i] = 0;
}

__global__ void uv_kernel(const float* __restrict__ W, const float* __restrict__ a) {
    int z = blockIdx.x;
    int k = threadIdx.x;
    const float* wrow = W + (size_t)(z * FF + k) * GN;
    const float* au = a + z * 2 * FF;
    const float* av = au + FF;
    float u = 0.f, v = 0.f;
    #pragma unroll 8
    for (int j = 0; j < FF; j++) {
        float w = wrow[j];
        u = fmaf(w, au[j], u);
        v = fmaf(w, av[j], v);
    }
    g_u[z * FF + k] = u;
    g_v[z * FF + k] = v;
}

__device__ __forceinline__ uint32_t pkh2(float a, float b) {
    __half2 t = __floats2half2_rn(a, b);
    return *(uint32_t*)&t;
}

// fused: scores (s_src/s_dst per hop) + fp16 conversion of X.
// warp per node; lane owns 8 CONTIGUOUS features [lane*8, lane*8+8).
__global__ void __launch_bounds__(256) scores_convX_kernel(const float* __restrict__ X) {
    __shared__ float su[KHOP][FF];
    __shared__ float sv[KHOP][FF];
    int tid = threadIdx.x;
    for (int i = tid; i < KHOP * FF; i += 256) {
        su[i / FF][i % FF] = g_u[i];
        sv[i / FF][i % FF] = g_v[i];
    }
    __syncthreads();
    int warp = tid >> 5, lane = tid & 31;
    int n = blockIdx.x * 8 + warp;
    if (n >= NN) return;
    const int f0 = lane * 8;
    float4 xa = *(const float4*)(X + (size_t)n * FF + f0);
    float4 xb = *(const float4*)(X + (size_t)n * FF + f0 + 4);
    // write fp16 row (coalesced uint4 per lane)
    uint4 xh;
    xh.x = pkh2(xa.x, xa.y); xh.y = pkh2(xa.z, xa.w);
    xh.z = pkh2(xb.x, xb.y); xh.w = pkh2(xb.z, xb.w);
    *(uint4*)(g_Xh + (size_t)n * FF + f0) = xh;
    float xr[8] = {xa.x, xa.y, xa.z, xa.w, xb.x, xb.y, xb.z, xb.w};
    #pragma unroll
    for (int z = 0; z < KHOP; z++) {
        float du = 0.f, dv = 0.f;
        #pragma unroll
        for (int j = 0; j < 8; j++) {
            du = fmaf(xr[j], su[z][f0 + j], du);
            dv = fmaf(xr[j], sv[z][f0 + j], dv);
        }
        #pragma unroll
        for (int off = 16; off > 0; off >>= 1) {
            du += __shfl_xor_sync(0xFFFFFFFFu, du, off);
            dv += __shfl_xor_sync(0xFFFFFFFFu, dv, off);
        }
        if (lane == 0) {
            g_s_src[z * NN + n] = du;
            g_s_dst[z * NN + n] = dv;
        }
    }
}

// 4 edges per thread via int4 (EE divisible by 4)
__global__ void hist_kernel(const int* __restrict__ kel) {
    int z = blockIdx.y;
    int e = (blockIdx.x * 256 + threadIdx.x) * 4;
    if (e >= EE) return;
    int4 s = __ldcs((const int4*)(kel + (size_t)z * 2 * EE + e));
    atomicAdd(&g_deg[z * NN + s.x], 1);
    atomicAdd(&g_deg[z * NN + s.y], 1);
    atomicAdd(&g_deg[z * NN + s.z], 1);
    atomicAdd(&g_deg[z * NN + s.w], 1);
}

// ---- 3-phase parallel scan over the whole 150K degree array ----
__global__ void __launch_bounds__(1024) scanA_kernel() {
    __shared__ int wsum[32];
    int b = blockIdx.x, tid = threadIdx.x, lane = tid & 31, wid = tid >> 5;
    int i = b * 1024 + tid;
    int v = (i < TOTN) ? g_deg[i] : 0;
    int x = v;
    #pragma unroll
    for (int off = 1; off < 32; off <<= 1) {
        int t = __shfl_up_sync(0xFFFFFFFFu, x, off);
        if (lane >= off) x += t;
    }
    if (lane == 31) wsum[wid] = x;
    __syncthreads();
    if (wid == 0) {
        int s = wsum[lane];
        #pragma unroll
        for (int off = 1; off < 32; off <<= 1) {
            int t = __shfl_up_sync(0xFFFFFFFFu, s, off);
            if (lane >= off) s += t;
        }
        wsum[lane] = s;
    }
    __syncthreads();
    int woff = wid ? wsum[wid - 1] : 0;
    if (i < TOTN) g_ptr[i] = woff + x - v;
    if (tid == 1023) g_bsum[b] = wsum[31];
}

__global__ void __launch_bounds__(256) scanB_kernel() {
    __shared__ int wsum[8];
    int tid = threadIdx.x, lane = tid & 31, wid = tid >> 5;
    int v = (tid < SCAN_BLOCKS) ? g_bsum[tid] : 0;
    int x = v;
    #pragma unroll
    for (int off = 1; off < 32; off <<= 1) {
        int t = __shfl_up_sync(0xFFFFFFFFu, x, off);
        if (lane >= off) x += t;
    }
    if (lane == 31) wsum[wid] = x;
    __syncthreads();
    if (wid == 0 && lane < 8) {
        int s = wsum[lane];
        #pragma unroll
        for (int off = 1; off < 8; off <<= 1) {
            int t = __shfl_up_sync(0xFFu, s, off);
            if (lane >= off) s += t;
        }
        wsum[lane] = s;
    }
    __syncthreads();
    int woff = wid ? wsum[wid - 1] : 0;
    if (tid < SCAN_BLOCKS) g_boff[tid] = woff + x - v;
}

__global__ void __launch_bounds__(1024) scanC_kernel() {
    int b = blockIdx.x;
    int i = b * 1024 + threadIdx.x;
    if (i >= TOTN) return;
    int z = (i >= 2 * NN) ? 2 : (i >= NN) ? 1 : 0;
    int val = g_ptr[i] + g_boff[b] - z * EE;
    g_ptr[i] = val;
    g_fill[i] = val;
}

// CSR build: 4 edges/thread, int4 index loads; no rowsum (computed in aggregate)
__global__ void build_kernel(const int* __restrict__ kel) {
    int z = blockIdx.y;
    int e = (blockIdx.x * 256 + threadIdx.x) * 4;
    if (e >= EE) return;
    int4 s4 = __ldcs((const int4*)(kel + (size_t)z * 2 * EE + e));
    int4 d4 = __ldcs((const int4*)(kel + (size_t)z * 2 * EE + EE + e));
    const int srcs[4] = {s4.x, s4.y, s4.z, s4.w};
    const int dsts[4] = {d4.x, d4.y, d4.z, d4.w};
    #pragma unroll
    for (int q = 0; q < 4; q++) {
        float sc = g_s_src[z * NN + srcs[q]] + g_s_dst[z * NN + dsts[q]];
        float l = sc > 0.f ? sc : 0.2f * sc;       // leaky_relu(alpha=0.2)
        float w = expf(-l);
        int idx = atomicAdd(&g_fill[z * NN + srcs[q]], 1);
        __stcs(&g_csr[(size_t)z * EE + idx], make_int2(dsts[q], __float_as_int(w)));
    }
}

__global__ void __launch_bounds__(256) convW_kernel(const float* __restrict__ W) {
    int idx = blockIdx.x * 256 + threadIdx.x;
    if (idx >= KHOP * FF * GN) return;
    int z = idx >> 16;
    int rem = idx & 65535;
    int k = rem >> 8;
    int n = rem & 255;
    float w = W[(size_t)(z * FF + k) * GN + n];
    g_Wth[z * 65536 + n * 256 + k] = __float2half_rn(w);
}

// ---------------- mma.sync fp16 GEMM (base-ISA HMMA; sm_103-safe) ----------------

#define SAW 40   // smem row pitch in halfs (80 B: 16B-aligned, conflict-free frag reads)

__device__ __forceinline__ void mma16816h(float* c, const uint32_t* a, const uint32_t* b) {
    asm volatile(
        "mma.sync.aligned.m16n8k16.row.col.f32.f16.f16.f32 "
        "{%0,%1,%2,%3}, {%4,%5,%6,%7}, {%8,%9}, {%0,%1,%2,%3};"
        : "+f"(c[0]), "+f"(c[1]), "+f"(c[2]), "+f"(c[3])
        : "r"(a[0]), "r"(a[1]), "r"(a[2]), "r"(a[3]), "r"(b[0]), "r"(b[1]));
}

__global__ void __launch_bounds__(256) gemm_mma_kernel() {
    __shared__ __half sA[128 * SAW];
    __shared__ __half sB[128 * SAW];

    const int tid = threadIdx.x;
    const int wid = tid >> 5, lane = tid & 31;
    const int g = lane >> 2, tg = lane & 3;
    const int warp_m = wid >> 2;
    const int warp_n = wid & 3;
    const int rowBase = blockIdx.x * 128;
    const int colBase = blockIdx.y * 128;
    const int z = blockIdx.z;

    const __half* Wth = g_Wth + (size_t)z * 65536;
    __half* Yh = g_Yh + (size_t)z * NN * FF;

    float c[4][4][4];
    #pragma unroll
    for (int mt = 0; mt < 4; mt++)
        #pragma unroll
        for (int nt = 0; nt < 4; nt++)
            #pragma unroll
            for (int q = 0; q < 4; q++) c[mt][nt][q] = 0.f;

    for (int kc = 0; kc < 8; kc++) {
        const int k0g = kc * 32;
        #pragma unroll
        for (int it = 0; it < 2; it++) {
            int q = tid + it * 256;
            int r = q >> 2, s = q & 3;
            int row_g = rowBase + r;
            uint4 va = make_uint4(0, 0, 0, 0);
            if (row_g < NN) va = *(const uint4*)(g_Xh + (size_t)row_g * FF + k0g + s * 8);
            *(uint4*)(sA + r * SAW + s * 8) = va;
        }
        #pragma unroll
        for (int it = 0; it < 2; it++) {
            int q = tid + it * 256;
            int r = q >> 2, s = q & 3;
            *(uint4*)(sB + r * SAW + s * 8) =
                *(const uint4*)(Wth + (size_t)(colBase + r) * 256 + k0g + s * 8);
        }
        __syncthreads();

        #pragma unroll
        for (int ks = 0; ks < 2; ks++) {
            const int k0 = ks * 16;
            uint32_t ah[4][4];
            #pragma unroll
            for (int mt = 0; mt < 4; mt++) {
                int r0 = warp_m * 64 + mt * 16 + g;
                int kk = k0 + tg * 2;
                ah[mt][0] = *(const uint32_t*)(sA + r0 * SAW + kk);
                ah[mt][1] = *(const uint32_t*)(sA + (r0 + 8) * SAW + kk);
                ah[mt][2] = *(const uint32_t*)(sA + r0 * SAW + kk + 8);
                ah[mt][3] = *(const uint32_t*)(sA + (r0 + 8) * SAW + kk + 8);
            }
            uint32_t bh[4][2];
            #pragma unroll
            for (int nt = 0; nt < 4; nt++) {
                int n0 = warp_n * 32 + nt * 8 + g;
                int kk = k0 + tg * 2;
                bh[nt][0] = *(const uint32_t*)(sB + n0 * SAW + kk);
                bh[nt][1] = *(const uint32_t*)(sB + n0 * SAW + kk + 8);
            }
            #pragma unroll
            for (int mt = 0; mt < 4; mt++)
                #pragma unroll
                for (int nt = 0; nt < 4; nt++)
                    mma16816h(c[mt][nt], ah[mt], bh[nt]);
        }
        __syncthreads();
    }

    #pragma unroll
    for (int mt = 0; mt < 4; mt++) {
        int r0 = rowBase + warp_m * 64 + mt * 16 + g;
        #pragma unroll
        for (int nt = 0; nt < 4; nt++) {
            int col = colBase + warp_n * 32 + nt * 8 + tg * 2;
            if (r0 < NN)
                *(uint32_t*)(Yh + (size_t)r0 * GN + col) = pkh2(c[mt][nt][0], c[mt][nt][1]);
            if (r0 + 8 < NN)
                *(uint32_t*)(Yh + (size_t)(r0 + 8) * GN + col) = pkh2(c[mt][nt][2], c[mt][nt][3]);
        }
    }
}

// ---------------- fused 3-hop aggregation, feature-split into 2 passes ----------------
// rowsum computed on the fly from broadcast weights (identical value, atomic-free)
__global__ void __launch_bounds__(256) aggregate_fused_kernel(float* __restrict__ out) {
    const int wid = threadIdx.x >> 5, lane = threadIdx.x & 31;
    const int n = blockIdx.x * 8 + wid;
    const int p = blockIdx.y;                    // feature half
    if (n >= NN) return;
    const int fo = p * 128 + lane * 4;

    float tot[4] = {0.f, 0.f, 0.f, 0.f};

    #pragma unroll
    for (int z = 0; z < KHOP; z++) {
        const int start = g_ptr[z * NN + n];
        const int d     = g_deg[z * NN + n];
        const int2* __restrict__ ce = g_csr + (size_t)z * EE + start;
        const __half* __restrict__ Yz = g_Yh + (size_t)z * NN * FF + fo;

        float acc[4] = {0.f, 0.f, 0.f, 0.f};
        float accw = 0.f;

        for (int base = 0; base < d; base += 32) {
            int cnt = min(32, d - base);
            int2 e = __ldcs(&ce[base + lane]);   // streaming: don't evict hot Y
            #pragma unroll 8
            for (int k = 0; k < cnt; k++) {
                int   dst = __shfl_sync(0xFFFFFFFFu, e.x, k);
                float w   = __int_as_float(__shfl_sync(0xFFFFFFFFu, e.y, k));
                accw += w;
                uint2 v = *(const uint2*)(Yz + (size_t)dst * FF);
                float2 f0 = __half22float2(*(__half2*)&v.x);
                float2 f1 = __half22float2(*(__half2*)&v.y);
                acc[0] = fmaf(w, f0.x, acc[0]);
                acc[1] = fmaf(w, f0.y, acc[1]);
                acc[2] = fmaf(w, f1.x, acc[2]);
                acc[3] = fmaf(w, f1.y, acc[3]);
            }
        }
        const float coef = (z == 0) ? 0.5f : (z == 1) ? 0.25f : 0.125f;
        float s = coef / accw;
        #pragma unroll
        for (int t = 0; t < 4; t++) tot[t] = fmaf(acc[t], s, tot[t]);
    }

    float4 o = make_float4(elu1(tot[0]), elu1(tot[1]), elu1(tot[2]), elu1(tot[3]));
    __stcs((float4*)(out + (size_t)n * FF + fo), o);
}

// ---------------- launch ----------------
extern "C" void kernel_launch(void* const* d_in, const int* in_sizes, int n_in,
                              void* d_out, int out_size) {
    const float* X   = (const float*)d_in[0];
    const int*   kel = (const int*)d_in[1];
    const float* W   = (const float*)d_in[2];
    const float* a   = (const float*)d_in[3];
    float* out = (float*)d_out;

    zero_kernel<<<(TOTN + 255) / 256, 256>>>();
    uv_kernel<<<KHOP, 256>>>(W, a);
    convW_kernel<<<(KHOP * FF * GN + 255) / 256, 256>>>(W);
    scores_convX_kernel<<<(NN + 7) / 8, 256>>>(X);
    hist_kernel<<<dim3((EE / 4 + 255) / 256, KHOP), 256>>>(kel);
    gemm_mma_kernel<<<dim3((NN + 127) / 128, GN / 128, KHOP), 256>>>();
    scanA_kernel<<<SCAN_BLOCKS, 1024>>>();
    scanB_kernel<<<1, 256>>>();
    scanC_kernel<<<SCAN_BLOCKS, 1024>>>();
    build_kernel<<<dim3((EE / 4 + 255) / 256, KHOP), 256>>>(kel);
    aggregate_fused_kernel<<<dim3((NN + 7) / 8, 2), 256>>>(out);
}